// round 6
// baseline (speedup 1.0000x reference)
#include <cuda_runtime.h>
#include <math.h>

// ---------------------------------------------------------------------------
// Problem constants: x[4,256,64,64], GROUPS=8, HEADS=4, d=64, N=HW=4096
// ---------------------------------------------------------------------------
#define BATCH    4
#define CH       256
#define NHEADS   4
#define DHEAD    64
#define NPOS     4096            // 64*64
#define GRP_ELEMS 131072         // 32 channels * 4096
#define GN_SPLIT 16
#define LOG2E_F  1.4426950408889634f

// Attention smem strides
#define SQ2 66   // u64 stride for duplicated-pair tiles (even -> 16B aligned)
#define SKS 68   // float stride for K tile / output staging
#define SVT 68   // float stride for transposed V tile

// Scratch (module-load allocated; no runtime allocation)
__device__ float  g_h[BATCH * CH * NPOS];          // 16 MB  normalized input
__device__ float  g_qkv[BATCH * 3 * CH * NPOS];    // 48 MB  q|k|v per batch
__device__ float  g_att[BATCH * CH * NPOS];        // 16 MB  attention output
__device__ float2 g_part[32 * GN_SPLIT];
__device__ float  g_mean[32];
__device__ float  g_rstd[32];

// ---------------------------------------------------------------------------
// Packed f32x2 helpers (FFMA2 path: ptxas will not auto-fuse; PTX-only)
// ---------------------------------------------------------------------------
typedef unsigned long long u64;

__device__ __forceinline__ u64 pack2(float lo, float hi) {
    u64 r;
    asm("mov.b64 %0, {%1, %2};" : "=l"(r) : "f"(lo), "f"(hi));
    return r;
}
__device__ __forceinline__ void unpack2(u64 v, float& lo, float& hi) {
    asm("mov.b64 {%0, %1}, %2;" : "=f"(lo), "=f"(hi) : "l"(v));
}
__device__ __forceinline__ void ffma2(u64& d, u64 a, u64 b) {
    asm("fma.rn.f32x2 %0, %1, %2, %0;" : "+l"(d) : "l"(a), "l"(b));
}
__device__ __forceinline__ void fmul2(u64& d, u64 a) {
    asm("mul.rn.f32x2 %0, %0, %1;" : "+l"(d) : "l"(a));
}

// ---------------------------------------------------------------------------
// GroupNorm: split partial reduction -> finalize -> apply
// ---------------------------------------------------------------------------
__global__ __launch_bounds__(256) void gn_partial_kernel(const float* __restrict__ x) {
    int bg = blockIdx.y, sp = blockIdx.x, tid = threadIdx.x;
    size_t base = (size_t)bg * GRP_ELEMS + (size_t)sp * (GRP_ELEMS / GN_SPLIT);
    const float4* p = (const float4*)(x + base);
    float s = 0.f, sq = 0.f;
#pragma unroll
    for (int it = 0; it < 8; it++) {
        float4 v = p[it * 256 + tid];
        s  += v.x + v.y + v.z + v.w;
        sq += v.x * v.x + v.y * v.y + v.z * v.z + v.w * v.w;
    }
    __shared__ float ss[8], ssq[8];
#pragma unroll
    for (int o = 16; o > 0; o >>= 1) {
        s  += __shfl_xor_sync(0xffffffffu, s,  o);
        sq += __shfl_xor_sync(0xffffffffu, sq, o);
    }
    if ((tid & 31) == 0) { ss[tid >> 5] = s; ssq[tid >> 5] = sq; }
    __syncthreads();
    if (tid < 8) {
        s = ss[tid]; sq = ssq[tid];
#pragma unroll
        for (int o = 4; o > 0; o >>= 1) {
            s  += __shfl_xor_sync(0xffu, s,  o);
            sq += __shfl_xor_sync(0xffu, sq, o);
        }
        if (tid == 0) g_part[bg * GN_SPLIT + sp] = make_float2(s, sq);
    }
}

__global__ __launch_bounds__(32) void gn_finalize_kernel() {
    int bg = blockIdx.x, t = threadIdx.x;
    float s = 0.f, sq = 0.f;
    if (t < GN_SPLIT) { float2 v = g_part[bg * GN_SPLIT + t]; s = v.x; sq = v.y; }
#pragma unroll
    for (int o = 16; o > 0; o >>= 1) {
        s  += __shfl_xor_sync(0xffffffffu, s,  o);
        sq += __shfl_xor_sync(0xffffffffu, sq, o);
    }
    if (t == 0) {
        const float inv = 1.0f / (float)GRP_ELEMS;
        float m   = s * inv;
        float var = sq * inv - m * m;
        g_mean[bg] = m;
        g_rstd[bg] = rsqrtf(var + 1e-5f);
    }
}

__global__ __launch_bounds__(256) void gn_apply_kernel(const float* __restrict__ x,
                                                       const float* __restrict__ gamma,
                                                       const float* __restrict__ beta) {
    int gi = blockIdx.x * 256 + threadIdx.x;      // float4 index
    size_t idx = (size_t)gi * 4;
    int ch = (int)((idx >> 12) & 255);            // (idx/4096) % 256
    int bg = (int)(idx >> 17);                    // idx / 131072
    float r  = g_rstd[bg];
    float ga = gamma[ch] * r;
    float be = beta[ch] - g_mean[bg] * ga;        // h = x*ga + be
    float4 v = *(const float4*)(x + idx);
    float4 o;
    o.x = v.x * ga + be; o.y = v.y * ga + be;
    o.z = v.z * ga + be; o.w = v.w * ga + be;
    *(float4*)(g_h + idx) = o;
}

// ---------------------------------------------------------------------------
// Tiled SGEMM:  C[b][m][n] = sum_k A[m][k] * B[b][k][n] + bias[m] (+ R[b][m][n])
// A row-major [M,K], B row-major [K,4096] per batch. BM=BN=64, BK=16,
// 256 threads, 4x4 micro-tile, FFMA2 inner loop with pre-duplicated A pairs.
// ---------------------------------------------------------------------------
template <bool RESID>
__global__ __launch_bounds__(256) void sgemm_kernel(const float* __restrict__ A,
                                                    const float* __restrict__ Bb,
                                                    const float* __restrict__ bias,
                                                    const float* __restrict__ Rb,
                                                    float* __restrict__ Cb,
                                                    int M, int K) {
    int b = blockIdx.z;
    const float* Bm = Bb + (size_t)b * K * NPOS;
    float*       Cm = Cb + (size_t)b * M * NPOS;
    int m0 = blockIdx.y * 64, n0 = blockIdx.x * 64;
    int tid = threadIdx.x, ty = tid >> 4, tx = tid & 15;
    __shared__ u64   As2[16 * SQ2];  // [k][m], duplicated (a,a) pairs
    __shared__ float Bs[16][64];     // [k][n]
    u64 acc2[4][2];                  // packed: [i][(j0,j1)|(j2,j3)]
#pragma unroll
    for (int i = 0; i < 4; i++) { acc2[i][0] = 0ull; acc2[i][1] = 0ull; }
    int arow = tid >> 2, acol = (tid & 3) * 4;
    int brow = tid >> 4, bcol = (tid & 15) * 4;
    for (int kt = 0; kt < K; kt += 16) {
        float4 a4 = *(const float4*)(A + (size_t)(m0 + arow) * K + kt + acol);
        As2[(acol + 0) * SQ2 + arow] = pack2(a4.x, a4.x);
        As2[(acol + 1) * SQ2 + arow] = pack2(a4.y, a4.y);
        As2[(acol + 2) * SQ2 + arow] = pack2(a4.z, a4.z);
        As2[(acol + 3) * SQ2 + arow] = pack2(a4.w, a4.w);
        float4 b4 = *(const float4*)(Bm + (size_t)(kt + brow) * NPOS + n0 + bcol);
        *(float4*)&Bs[brow][bcol] = b4;
        __syncthreads();
#pragma unroll
        for (int kk = 0; kk < 16; kk++) {
            ulonglong2 aA = *(const ulonglong2*)(As2 + kk * SQ2 + ty * 4);
            ulonglong2 aB = *(const ulonglong2*)(As2 + kk * SQ2 + ty * 4 + 2);
            ulonglong2 bb = *(const ulonglong2*)(&Bs[kk][tx * 4]);
            ffma2(acc2[0][0], aA.x, bb.x); ffma2(acc2[0][1], aA.x, bb.y);
            ffma2(acc2[1][0], aA.y, bb.x); ffma2(acc2[1][1], aA.y, bb.y);
            ffma2(acc2[2][0], aB.x, bb.x); ffma2(acc2[2][1], aB.x, bb.y);
            ffma2(acc2[3][0], aB.y, bb.x); ffma2(acc2[3][1], aB.y, bb.y);
        }
        __syncthreads();
    }
#pragma unroll
    for (int i = 0; i < 4; i++) {
        int m = m0 + ty * 4 + i;
        float bi = bias[m];
        float4 o;
        unpack2(acc2[i][0], o.x, o.y);
        unpack2(acc2[i][1], o.z, o.w);
        o.x += bi; o.y += bi; o.z += bi; o.w += bi;
        if (RESID) {
            float4 r4 = *(const float4*)(Rb + (size_t)b * M * NPOS + (size_t)m * NPOS + n0 + tx * 4);
            o.x += r4.x; o.y += r4.y; o.z += r4.z; o.w += r4.w;
        }
        *(float4*)(Cm + (size_t)m * NPOS + n0 + tx * 4) = o;
    }
}

// ---------------------------------------------------------------------------
// Flash attention (fp32, online softmax in base-2 domain, FFMA2 inner loops
// with pre-duplicated broadcast operands and reinterpret-cast value pairs).
// Block = 64 queries x d=64 for one (b,head); loops over 64 key tiles.
// Threads: 16x16, each owns 4x4 of S and 4x4 of O.
// Smem layout (bytes, all 16B-aligned):
//   Qs2  u64[64*66]  (Q duplicated pairs)     @ 0       33792
//   Ps2  u64[64*66]  (P duplicated pairs)     @ 33792   33792
//   Ks   f32[64*68]  (K rows; also O staging) @ 67584   17408
//   Vt   f32[64*68]  (V transposed [kj][dd])  @ 84992   17408
// Total 102400 B -> 2 CTAs/SM.
// ---------------------------------------------------------------------------
__device__ __forceinline__ float ex2f(float x) {
    float r;
    asm("ex2.approx.ftz.f32 %0, %1;" : "=f"(r) : "f"(x));
    return r;
}

#define ATTN_SMEM 102400

__global__ __launch_bounds__(256) void attn_kernel(const float* __restrict__ qkv,
                                                   float* __restrict__ out) {
    extern __shared__ char smraw[];
    u64*   Qs2 = (u64*)smraw;
    u64*   Ps2 = (u64*)(smraw + 33792);
    float* Ks  = (float*)(smraw + 67584);
    float* Vt  = (float*)(smraw + 84992);

    int tid = threadIdx.x, ty = tid >> 4, tx = tid & 15;
    int bh = blockIdx.y;
    int b = bh >> 2, head = bh & 3;
    int q0 = blockIdx.x * 64;
    const float* qb = qkv + ((size_t)b * 3 * CH + head * DHEAD) * NPOS;
    const float* kb = qb + (size_t)CH * NPOS;
    const float* vb = qb + (size_t)2 * CH * NPOS;
    const float QSC = 0.125f * LOG2E_F;   // 1/sqrt(d) * log2(e)

    // Load + scale Q tile, duplicated pairs: Qs2[dd][qi] = (q,q)
#pragma unroll
    for (int it = 0; it < 4; it++) {
        int n = it * 1024 + tid * 4;
        int dd = n >> 6, qi = n & 63;
        float4 v = *(const float4*)(qb + (size_t)dd * NPOS + q0 + qi);
        v.x *= QSC; v.y *= QSC; v.z *= QSC; v.w *= QSC;
        ulonglong2 lo, hi;
        lo.x = pack2(v.x, v.x); lo.y = pack2(v.y, v.y);
        hi.x = pack2(v.z, v.z); hi.y = pack2(v.w, v.w);
        *(ulonglong2*)(Qs2 + dd * SQ2 + qi)     = lo;
        *(ulonglong2*)(Qs2 + dd * SQ2 + qi + 2) = hi;
    }

    float m[4], l[4];
    u64 oAcc[4][2];   // packed O accumulators: [i][(j0,j1)|(j2,j3)]
#pragma unroll
    for (int i = 0; i < 4; i++) {
        m[i] = -1e30f; l[i] = 0.f;
        oAcc[i][0] = 0ull; oAcc[i][1] = 0ull;
    }

    for (int kt = 0; kt < 64; kt++) {
        int k0 = kt * 64;
        // Load K rows (float4) and V transposed (4 scalar scatter stores)
#pragma unroll
        for (int it = 0; it < 4; it++) {
            int n = it * 1024 + tid * 4;
            int dd = n >> 6, kj = n & 63;
            float4 k4 = *(const float4*)(kb + (size_t)dd * NPOS + k0 + kj);
            *(float4*)(Ks + dd * SKS + kj) = k4;
            float4 v4 = *(const float4*)(vb + (size_t)dd * NPOS + k0 + kj);
            Vt[(kj + 0) * SVT + dd] = v4.x;
            Vt[(kj + 1) * SVT + dd] = v4.y;
            Vt[(kj + 2) * SVT + dd] = v4.z;
            Vt[(kj + 3) * SVT + dd] = v4.w;
        }
        __syncthreads();

        // S = Q.K^T (scaled, base-2 domain): 3 LDS.128 + 8 FFMA2 per dd
        u64 sAcc[4][2] = {{0ull, 0ull}, {0ull, 0ull}, {0ull, 0ull}, {0ull, 0ull}};
#pragma unroll 8
        for (int dd = 0; dd < 64; dd++) {
            ulonglong2 aA = *(const ulonglong2*)(Qs2 + dd * SQ2 + ty * 4);
            ulonglong2 aB = *(const ulonglong2*)(Qs2 + dd * SQ2 + ty * 4 + 2);
            ulonglong2 bb = *(const ulonglong2*)(Ks + dd * SKS + tx * 4);
            ffma2(sAcc[0][0], aA.x, bb.x); ffma2(sAcc[0][1], aA.x, bb.y);
            ffma2(sAcc[1][0], aA.y, bb.x); ffma2(sAcc[1][1], aA.y, bb.y);
            ffma2(sAcc[2][0], aB.x, bb.x); ffma2(sAcc[2][1], aB.x, bb.y);
            ffma2(sAcc[3][0], aB.y, bb.x); ffma2(sAcc[3][1], aB.y, bb.y);
        }
        float s[4][4];
#pragma unroll
        for (int i = 0; i < 4; i++) {
            unpack2(sAcc[i][0], s[i][0], s[i][1]);
            unpack2(sAcc[i][1], s[i][2], s[i][3]);
        }

        // Online softmax update (rows spread over 16 tx lanes)
#pragma unroll
        for (int i = 0; i < 4; i++) {
            float rm = fmaxf(fmaxf(s[i][0], s[i][1]), fmaxf(s[i][2], s[i][3]));
#pragma unroll
            for (int off = 8; off > 0; off >>= 1)
                rm = fmaxf(rm, __shfl_xor_sync(0xffffffffu, rm, off, 16));
            float mn = fmaxf(m[i], rm);
            float al = ex2f(m[i] - mn);
            float rs = 0.f;
#pragma unroll
            for (int j = 0; j < 4; j++) {
                float e = ex2f(s[i][j] - mn);
                s[i][j] = e;
                rs += e;
            }
#pragma unroll
            for (int off = 8; off > 0; off >>= 1)
                rs += __shfl_xor_sync(0xffffffffu, rs, off, 16);
            l[i] = l[i] * al + rs;
            m[i] = mn;
            u64 al2 = pack2(al, al);
            fmul2(oAcc[i][0], al2);
            fmul2(oAcc[i][1], al2);
        }

        // P -> smem transposed + duplicated: Ps2[kj][qi] = (p,p)
#pragma unroll
        for (int j = 0; j < 4; j++) {
            ulonglong2 lo, hi;
            lo.x = pack2(s[0][j], s[0][j]); lo.y = pack2(s[1][j], s[1][j]);
            hi.x = pack2(s[2][j], s[2][j]); hi.y = pack2(s[3][j], s[3][j]);
            u64* pd = Ps2 + (tx * 4 + j) * SQ2 + ty * 4;
            *(ulonglong2*)pd       = lo;
            *(ulonglong2*)(pd + 2) = hi;
        }
        __syncthreads();

        // O += P.V : 3 LDS.128 + 8 FFMA2 per kk
#pragma unroll 8
        for (int kk = 0; kk < 64; kk++) {
            ulonglong2 pA = *(const ulonglong2*)(Ps2 + kk * SQ2 + ty * 4);
            ulonglong2 pB = *(const ulonglong2*)(Ps2 + kk * SQ2 + ty * 4 + 2);
            ulonglong2 vv = *(const ulonglong2*)(Vt + kk * SVT + tx * 4);
            ffma2(oAcc[0][0], pA.x, vv.x); ffma2(oAcc[0][1], pA.x, vv.y);
            ffma2(oAcc[1][0], pA.y, vv.x); ffma2(oAcc[1][1], pA.y, vv.y);
            ffma2(oAcc[2][0], pB.x, vv.x); ffma2(oAcc[2][1], pB.x, vv.y);
            ffma2(oAcc[3][0], pB.y, vv.x); ffma2(oAcc[3][1], pB.y, vv.y);
        }
        __syncthreads();
    }

    // Normalize (packed), unpack, stage through Ks region for coalesced output
    float o[4][4];
#pragma unroll
    for (int i = 0; i < 4; i++) {
        float inv = 1.0f / l[i];
        u64 inv2 = pack2(inv, inv);
        fmul2(oAcc[i][0], inv2);
        fmul2(oAcc[i][1], inv2);
        unpack2(oAcc[i][0], o[i][0], o[i][1]);
        unpack2(oAcc[i][1], o[i][2], o[i][3]);
    }
#pragma unroll
    for (int j = 0; j < 4; j++) {
        float4 q4;
        q4.x = o[0][j]; q4.y = o[1][j]; q4.z = o[2][j]; q4.w = o[3][j];
        *(float4*)(Ks + (tx * 4 + j) * SKS + ty * 4) = q4;   // Os[dd][qi]
    }
    __syncthreads();
    float* ob = out + ((size_t)b * CH + head * DHEAD) * NPOS;
#pragma unroll
    for (int it = 0; it < 4; it++) {
        int n = it * 1024 + tid * 4;
        int dd = n >> 6, qi = n & 63;
        float4 v = *(const float4*)(Ks + dd * SKS + qi);
        *(float4*)(ob + (size_t)dd * NPOS + q0 + qi) = v;
    }
}

// ---------------------------------------------------------------------------
// Launcher (graph-capturable: kernel launches only)
// ---------------------------------------------------------------------------
extern "C" void kernel_launch(void* const* d_in, const int* in_sizes, int n_in,
                              void* d_out, int out_size) {
    const float* x      = (const float*)d_in[0];
    const float* norm_w = (const float*)d_in[1];
    const float* norm_b = (const float*)d_in[2];
    const float* qkv_w  = (const float*)d_in[3];
    const float* qkv_b  = (const float*)d_in[4];
    const float* proj_w = (const float*)d_in[5];
    const float* proj_b = (const float*)d_in[6];
    float* out = (float*)d_out;

    float *hbuf = nullptr, *qkvbuf = nullptr, *attbuf = nullptr;
    cudaGetSymbolAddress((void**)&hbuf, g_h);
    cudaGetSymbolAddress((void**)&qkvbuf, g_qkv);
    cudaGetSymbolAddress((void**)&attbuf, g_att);

    // GroupNorm
    gn_partial_kernel<<<dim3(GN_SPLIT, 32), 256>>>(x);
    gn_finalize_kernel<<<32, 32>>>();
    gn_apply_kernel<<<(BATCH * CH * NPOS) / (256 * 4), 256>>>(x, norm_w, norm_b);

    // QKV projection: [768,256] x [256,4096] per batch
    sgemm_kernel<false><<<dim3(NPOS / 64, 768 / 64, BATCH), 256>>>(
        qkv_w, hbuf, qkv_b, nullptr, qkvbuf, 3 * CH, CH);

    // Attention
    cudaFuncSetAttribute(attn_kernel, cudaFuncAttributeMaxDynamicSharedMemorySize, ATTN_SMEM);
    attn_kernel<<<dim3(NPOS / 64, BATCH * NHEADS), 256, ATTN_SMEM>>>(qkvbuf, attbuf);

    // Output projection + bias + residual
    sgemm_kernel<true><<<dim3(NPOS / 64, CH / 64, BATCH), 256>>>(
        proj_w, attbuf, proj_b, x, out, CH, CH);
}

// round 10
// speedup vs baseline: 1.2060x; 1.2060x over previous
#include <cuda_runtime.h>
#include <math.h>

// ---------------------------------------------------------------------------
// Problem constants: x[4,256,64,64], GROUPS=8, HEADS=4, d=64, N=HW=4096
// ---------------------------------------------------------------------------
#define BATCH    4
#define CH       256
#define NHEADS   4
#define DHEAD    64
#define NPOS     4096            // 64*64
#define GRP_ELEMS 131072         // 32 channels * 4096
#define GN_SPLIT 16
#define LOG2E_F  1.4426950408889634f

// Attention smem strides
#define SQ2 66   // u64 stride for duplicated-pair tiles (even -> 16B-aligned rows)
#define SKS 68   // float stride for K tile / output staging
#define SVT 68   // float stride for transposed V tile

// Scratch (module-load allocated; no runtime allocation)
__device__ float  g_h[BATCH * CH * NPOS];          // 16 MB  normalized input
__device__ float  g_qkv[BATCH * 3 * CH * NPOS];    // 48 MB  q|k|v per batch
__device__ float  g_att[BATCH * CH * NPOS];        // 16 MB  attention output
__device__ float2 g_part[32 * GN_SPLIT];
__device__ float  g_mean[32];
__device__ float  g_rstd[32];

// ---------------------------------------------------------------------------
// Packed f32x2 helpers (FFMA2 path: ptxas will not auto-fuse; PTX-only)
// ---------------------------------------------------------------------------
typedef unsigned long long u64;

__device__ __forceinline__ u64 pack2(float lo, float hi) {
    u64 r;
    asm("mov.b64 %0, {%1, %2};" : "=l"(r) : "f"(lo), "f"(hi));
    return r;
}
__device__ __forceinline__ void unpack2(u64 v, float& lo, float& hi) {
    asm("mov.b64 {%0, %1}, %2;" : "=f"(lo), "=f"(hi) : "l"(v));
}
__device__ __forceinline__ void ffma2(u64& d, u64 a, u64 b) {
    asm("fma.rn.f32x2 %0, %1, %2, %0;" : "+l"(d) : "l"(a), "l"(b));
}
__device__ __forceinline__ void fmul2(u64& d, u64 a) {
    asm("mul.rn.f32x2 %0, %0, %1;" : "+l"(d) : "l"(a));
}
// Scalar 8-byte shared load, pinned as ld.shared.b64 (1 wavefront when the
// warp touches <=2 distinct addresses; ptxas cannot merge asm into LDS.128).
__device__ __forceinline__ u64 lds_u64(unsigned addr) {
    u64 r;
    asm("ld.shared.b64 %0, [%1];" : "=l"(r) : "r"(addr));
    return r;
}

// ---------------------------------------------------------------------------
// GroupNorm: split partial reduction -> finalize -> apply
// ---------------------------------------------------------------------------
__global__ __launch_bounds__(256) void gn_partial_kernel(const float* __restrict__ x) {
    int bg = blockIdx.y, sp = blockIdx.x, tid = threadIdx.x;
    size_t base = (size_t)bg * GRP_ELEMS + (size_t)sp * (GRP_ELEMS / GN_SPLIT);
    const float4* p = (const float4*)(x + base);
    float s = 0.f, sq = 0.f;
#pragma unroll
    for (int it = 0; it < 8; it++) {
        float4 v = p[it * 256 + tid];
        s  += v.x + v.y + v.z + v.w;
        sq += v.x * v.x + v.y * v.y + v.z * v.z + v.w * v.w;
    }
    __shared__ float ss[8], ssq[8];
#pragma unroll
    for (int o = 16; o > 0; o >>= 1) {
        s  += __shfl_xor_sync(0xffffffffu, s,  o);
        sq += __shfl_xor_sync(0xffffffffu, sq, o);
    }
    if ((tid & 31) == 0) { ss[tid >> 5] = s; ssq[tid >> 5] = sq; }
    __syncthreads();
    if (tid < 8) {
        s = ss[tid]; sq = ssq[tid];
#pragma unroll
        for (int o = 4; o > 0; o >>= 1) {
            s  += __shfl_xor_sync(0xffu, s,  o);
            sq += __shfl_xor_sync(0xffu, sq, o);
        }
        if (tid == 0) g_part[bg * GN_SPLIT + sp] = make_float2(s, sq);
    }
}

__global__ __launch_bounds__(32) void gn_finalize_kernel() {
    int bg = blockIdx.x, t = threadIdx.x;
    float s = 0.f, sq = 0.f;
    if (t < GN_SPLIT) { float2 v = g_part[bg * GN_SPLIT + t]; s = v.x; sq = v.y; }
#pragma unroll
    for (int o = 16; o > 0; o >>= 1) {
        s  += __shfl_xor_sync(0xffffffffu, s,  o);
        sq += __shfl_xor_sync(0xffffffffu, sq, o);
    }
    if (t == 0) {
        const float inv = 1.0f / (float)GRP_ELEMS;
        float m   = s * inv;
        float var = sq * inv - m * m;
        g_mean[bg] = m;
        g_rstd[bg] = rsqrtf(var + 1e-5f);
    }
}

__global__ __launch_bounds__(256) void gn_apply_kernel(const float* __restrict__ x,
                                                       const float* __restrict__ gamma,
                                                       const float* __restrict__ beta) {
    int gi = blockIdx.x * 256 + threadIdx.x;      // float4 index
    size_t idx = (size_t)gi * 4;
    int ch = (int)((idx >> 12) & 255);            // (idx/4096) % 256
    int bg = (int)(idx >> 17);                    // idx / 131072
    float r  = g_rstd[bg];
    float ga = gamma[ch] * r;
    float be = beta[ch] - g_mean[bg] * ga;        // h = x*ga + be
    float4 v = *(const float4*)(x + idx);
    float4 o;
    o.x = v.x * ga + be; o.y = v.y * ga + be;
    o.z = v.z * ga + be; o.w = v.w * ga + be;
    *(float4*)(g_h + idx) = o;
}

// ---------------------------------------------------------------------------
// Tiled SGEMM:  C[b][m][n] = sum_k A[m][k] * B[b][k][n] + bias[m] (+ R[b][m][n])
// A row-major [M,K], B row-major [K,4096] per batch. BM=BN=64, BK=16,
// 256 threads, 4x4 micro-tile. FFMA2 with scalar-u64 broadcast loads.
// ---------------------------------------------------------------------------
template <bool RESID>
__global__ __launch_bounds__(256) void sgemm_kernel(const float* __restrict__ A,
                                                    const float* __restrict__ Bb,
                                                    const float* __restrict__ bias,
                                                    const float* __restrict__ Rb,
                                                    float* __restrict__ Cb,
                                                    int M, int K) {
    int b = blockIdx.z;
    const float* Bm = Bb + (size_t)b * K * NPOS;
    float*       Cm = Cb + (size_t)b * M * NPOS;
    int m0 = blockIdx.y * 64, n0 = blockIdx.x * 64;
    int tid = threadIdx.x, ty = tid >> 4, tx = tid & 15;
    __shared__ u64   As2[16 * SQ2];  // [k][m], duplicated (a,a) pairs
    __shared__ float Bs[16][64];     // [k][n]
    unsigned as2_base = (unsigned)__cvta_generic_to_shared(As2) + (unsigned)(ty * 4) * 8u;
    u64 acc2[4][2];                  // packed: [i][(j0,j1)|(j2,j3)]
#pragma unroll
    for (int i = 0; i < 4; i++) { acc2[i][0] = 0ull; acc2[i][1] = 0ull; }
    int arow = tid >> 2, acol = (tid & 3) * 4;
    int brow = tid >> 4, bcol = (tid & 15) * 4;
    for (int kt = 0; kt < K; kt += 16) {
        float4 a4 = *(const float4*)(A + (size_t)(m0 + arow) * K + kt + acol);
        As2[(acol + 0) * SQ2 + arow] = pack2(a4.x, a4.x);
        As2[(acol + 1) * SQ2 + arow] = pack2(a4.y, a4.y);
        As2[(acol + 2) * SQ2 + arow] = pack2(a4.z, a4.z);
        As2[(acol + 3) * SQ2 + arow] = pack2(a4.w, a4.w);
        float4 b4 = *(const float4*)(Bm + (size_t)(kt + brow) * NPOS + n0 + bcol);
        *(float4*)&Bs[brow][bcol] = b4;
        __syncthreads();
#pragma unroll
        for (int kk = 0; kk < 16; kk++) {
            unsigned aaddr = as2_base + (unsigned)(kk * SQ2) * 8u;
            u64 a0 = lds_u64(aaddr);
            u64 a1 = lds_u64(aaddr + 8u);
            u64 a2 = lds_u64(aaddr + 16u);
            u64 a3 = lds_u64(aaddr + 24u);
            ulonglong2 bb = *(const ulonglong2*)(&Bs[kk][tx * 4]);
            ffma2(acc2[0][0], a0, bb.x); ffma2(acc2[0][1], a0, bb.y);
            ffma2(acc2[1][0], a1, bb.x); ffma2(acc2[1][1], a1, bb.y);
            ffma2(acc2[2][0], a2, bb.x); ffma2(acc2[2][1], a2, bb.y);
            ffma2(acc2[3][0], a3, bb.x); ffma2(acc2[3][1], a3, bb.y);
        }
        __syncthreads();
    }
#pragma unroll
    for (int i = 0; i < 4; i++) {
        int m = m0 + ty * 4 + i;
        float bi = bias[m];
        float4 o;
        unpack2(acc2[i][0], o.x, o.y);
        unpack2(acc2[i][1], o.z, o.w);
        o.x += bi; o.y += bi; o.z += bi; o.w += bi;
        if (RESID) {
            float4 r4 = *(const float4*)(Rb + (size_t)b * M * NPOS + (size_t)m * NPOS + n0 + tx * 4);
            o.x += r4.x; o.y += r4.y; o.z += r4.z; o.w += r4.w;
        }
        *(float4*)(Cm + (size_t)m * NPOS + n0 + tx * 4) = o;
    }
}

// ---------------------------------------------------------------------------
// Flash attention (fp32, online softmax, base-2 domain, FFMA2 inner loops).
// Block = 64 queries x d=64 for one (b,head); loops over 64 key tiles.
// Threads: 16x16, each owns 4x4 of S and 4x4 of O.
// Inner loops: 4x ld.shared.b64 (broadcast pairs, 1 wf each) + 1 LDS.128
// (value rows, 2 wf) + 8 FFMA2.
// Smem layout (bytes, all 16B-aligned):
//   Qs2  u64[64*66]  (Q duplicated pairs)     @ 0       33792
//   Ps2  u64[64*66]  (P duplicated pairs)     @ 33792   33792
//   Ks   f32[64*68]  (K rows; also O staging) @ 67584   17408
//   Vt   f32[64*68]  (V transposed [kj][dd])  @ 84992   17408
// Total 102400 B -> 2 CTAs/SM.
// ---------------------------------------------------------------------------
__device__ __forceinline__ float ex2f(float x) {
    float r;
    asm("ex2.approx.ftz.f32 %0, %1;" : "=f"(r) : "f"(x));
    return r;
}

#define ATTN_SMEM 102400

__global__ __launch_bounds__(256) void attn_kernel(const float* __restrict__ qkv,
                                                   float* __restrict__ out) {
    extern __shared__ char smraw[];
    u64*   Qs2 = (u64*)smraw;
    u64*   Ps2 = (u64*)(smraw + 33792);
    float* Ks  = (float*)(smraw + 67584);
    float* Vt  = (float*)(smraw + 84992);

    int tid = threadIdx.x, ty = tid >> 4, tx = tid & 15;
    unsigned q2_base = (unsigned)__cvta_generic_to_shared(Qs2) + (unsigned)(ty * 4) * 8u;
    unsigned p2_base = (unsigned)__cvta_generic_to_shared(Ps2) + (unsigned)(ty * 4) * 8u;

    int bh = blockIdx.y;
    int b = bh >> 2, head = bh & 3;
    int q0 = blockIdx.x * 64;
    const float* qb = qkv + ((size_t)b * 3 * CH + head * DHEAD) * NPOS;
    const float* kb = qb + (size_t)CH * NPOS;
    const float* vb = qb + (size_t)2 * CH * NPOS;
    const float QSC = 0.125f * LOG2E_F;   // 1/sqrt(d) * log2(e)

    // V loader mapping: dd-contiguous stores (low-conflict STS.128)
    int vkj  = tid & 63;        // key index this thread owns
    int vgrp = tid >> 6;        // 0..3 -> dd group base

    // Load + scale Q tile, duplicated pairs: Qs2[dd][qi] = (q,q)
#pragma unroll
    for (int it = 0; it < 4; it++) {
        int n = it * 1024 + tid * 4;
        int dd = n >> 6, qi = n & 63;
        float4 v = *(const float4*)(qb + (size_t)dd * NPOS + q0 + qi);
        v.x *= QSC; v.y *= QSC; v.z *= QSC; v.w *= QSC;
        ulonglong2 lo, hi;
        lo.x = pack2(v.x, v.x); lo.y = pack2(v.y, v.y);
        hi.x = pack2(v.z, v.z); hi.y = pack2(v.w, v.w);
        *(ulonglong2*)(Qs2 + dd * SQ2 + qi)     = lo;
        *(ulonglong2*)(Qs2 + dd * SQ2 + qi + 2) = hi;
    }

    float m[4], l[4];
    u64 oAcc[4][2];   // packed O accumulators: [i][(j0,j1)|(j2,j3)]
#pragma unroll
    for (int i = 0; i < 4; i++) {
        m[i] = -1e30f; l[i] = 0.f;
        oAcc[i][0] = 0ull; oAcc[i][1] = 0ull;
    }

    for (int kt = 0; kt < 64; kt++) {
        int k0 = kt * 64;
        // K rows: natural layout, LDG.128 -> STS.128
#pragma unroll
        for (int it = 0; it < 4; it++) {
            int n = it * 1024 + tid * 4;
            int dd = n >> 6, kj = n & 63;
            float4 k4 = *(const float4*)(kb + (size_t)dd * NPOS + k0 + kj);
            *(float4*)(Ks + dd * SKS + kj) = k4;
        }
        // V transposed: coalesced scalar LDG, dd-contiguous STS.128
#pragma unroll
        for (int it = 0; it < 4; it++) {
            int dd0 = vgrp * 16 + it * 4;
            const float* vsrc = vb + k0 + vkj;
            float4 v;
            v.x = vsrc[(size_t)(dd0 + 0) * NPOS];
            v.y = vsrc[(size_t)(dd0 + 1) * NPOS];
            v.z = vsrc[(size_t)(dd0 + 2) * NPOS];
            v.w = vsrc[(size_t)(dd0 + 3) * NPOS];
            *(float4*)(Vt + vkj * SVT + dd0) = v;
        }
        __syncthreads();

        // S = Q.K^T (scaled, base-2 domain)
        u64 sAcc[4][2] = {{0ull, 0ull}, {0ull, 0ull}, {0ull, 0ull}, {0ull, 0ull}};
#pragma unroll 8
        for (int dd = 0; dd < 64; dd++) {
            unsigned qaddr = q2_base + (unsigned)(dd * SQ2) * 8u;
            u64 a0 = lds_u64(qaddr);
            u64 a1 = lds_u64(qaddr + 8u);
            u64 a2 = lds_u64(qaddr + 16u);
            u64 a3 = lds_u64(qaddr + 24u);
            ulonglong2 bb = *(const ulonglong2*)(Ks + dd * SKS + tx * 4);
            ffma2(sAcc[0][0], a0, bb.x); ffma2(sAcc[0][1], a0, bb.y);
            ffma2(sAcc[1][0], a1, bb.x); ffma2(sAcc[1][1], a1, bb.y);
            ffma2(sAcc[2][0], a2, bb.x); ffma2(sAcc[2][1], a2, bb.y);
            ffma2(sAcc[3][0], a3, bb.x); ffma2(sAcc[3][1], a3, bb.y);
        }
        float s[4][4];
#pragma unroll
        for (int i = 0; i < 4; i++) {
            unpack2(sAcc[i][0], s[i][0], s[i][1]);
            unpack2(sAcc[i][1], s[i][2], s[i][3]);
        }

        // Online softmax update (rows spread over 16 tx lanes)
#pragma unroll
        for (int i = 0; i < 4; i++) {
            float rm = fmaxf(fmaxf(s[i][0], s[i][1]), fmaxf(s[i][2], s[i][3]));
#pragma unroll
            for (int off = 8; off > 0; off >>= 1)
                rm = fmaxf(rm, __shfl_xor_sync(0xffffffffu, rm, off, 16));
            float mn = fmaxf(m[i], rm);
            float al = ex2f(m[i] - mn);
            float rs = 0.f;
#pragma unroll
            for (int j = 0; j < 4; j++) {
                float e = ex2f(s[i][j] - mn);
                s[i][j] = e;
                rs += e;
            }
#pragma unroll
            for (int off = 8; off > 0; off >>= 1)
                rs += __shfl_xor_sync(0xffffffffu, rs, off, 16);
            l[i] = l[i] * al + rs;
            m[i] = mn;
            u64 al2 = pack2(al, al);
            fmul2(oAcc[i][0], al2);
            fmul2(oAcc[i][1], al2);
        }

        // P -> smem transposed + duplicated: Ps2[kj][qi] = (p,p)
#pragma unroll
        for (int j = 0; j < 4; j++) {
            ulonglong2 lo, hi;
            lo.x = pack2(s[0][j], s[0][j]); lo.y = pack2(s[1][j], s[1][j]);
            hi.x = pack2(s[2][j], s[2][j]); hi.y = pack2(s[3][j], s[3][j]);
            u64* pd = Ps2 + (tx * 4 + j) * SQ2 + ty * 4;
            *(ulonglong2*)pd       = lo;
            *(ulonglong2*)(pd + 2) = hi;
        }
        __syncthreads();

        // O += P.V
#pragma unroll 8
        for (int kk = 0; kk < 64; kk++) {
            unsigned paddr = p2_base + (unsigned)(kk * SQ2) * 8u;
            u64 p0 = lds_u64(paddr);
            u64 p1 = lds_u64(paddr + 8u);
            u64 p2 = lds_u64(paddr + 16u);
            u64 p3 = lds_u64(paddr + 24u);
            ulonglong2 vv = *(const ulonglong2*)(Vt + kk * SVT + tx * 4);
            ffma2(oAcc[0][0], p0, vv.x); ffma2(oAcc[0][1], p0, vv.y);
            ffma2(oAcc[1][0], p1, vv.x); ffma2(oAcc[1][1], p1, vv.y);
            ffma2(oAcc[2][0], p2, vv.x); ffma2(oAcc[2][1], p2, vv.y);
            ffma2(oAcc[3][0], p3, vv.x); ffma2(oAcc[3][1], p3, vv.y);
        }
        __syncthreads();
    }

    // Normalize (packed), unpack, stage through Ks region for coalesced output
    float o[4][4];
#pragma unroll
    for (int i = 0; i < 4; i++) {
        float inv = 1.0f / l[i];
        u64 inv2 = pack2(inv, inv);
        fmul2(oAcc[i][0], inv2);
        fmul2(oAcc[i][1], inv2);
        unpack2(oAcc[i][0], o[i][0], o[i][1]);
        unpack2(oAcc[i][1], o[i][2], o[i][3]);
    }
#pragma unroll
    for (int j = 0; j < 4; j++) {
        float4 q4;
        q4.x = o[0][j]; q4.y = o[1][j]; q4.z = o[2][j]; q4.w = o[3][j];
        *(float4*)(Ks + (tx * 4 + j) * SKS + ty * 4) = q4;   // Os[dd][qi]
    }
    __syncthreads();
    float* ob = out + ((size_t)b * CH + head * DHEAD) * NPOS;
#pragma unroll
    for (int it = 0; it < 4; it++) {
        int n = it * 1024 + tid * 4;
        int dd = n >> 6, qi = n & 63;
        float4 v = *(const float4*)(Ks + dd * SKS + qi);
        *(float4*)(ob + (size_t)dd * NPOS + q0 + qi) = v;
    }
}

// ---------------------------------------------------------------------------
// Launcher (graph-capturable: kernel launches only)
// ---------------------------------------------------------------------------
extern "C" void kernel_launch(void* const* d_in, const int* in_sizes, int n_in,
                              void* d_out, int out_size) {
    const float* x      = (const float*)d_in[0];
    const float* norm_w = (const float*)d_in[1];
    const float* norm_b = (const float*)d_in[2];
    const float* qkv_w  = (const float*)d_in[3];
    const float* qkv_b  = (const float*)d_in[4];
    const float* proj_w = (const float*)d_in[5];
    const float* proj_b = (const float*)d_in[6];
    float* out = (float*)d_out;

    float *hbuf = nullptr, *qkvbuf = nullptr, *attbuf = nullptr;
    cudaGetSymbolAddress((void**)&hbuf, g_h);
    cudaGetSymbolAddress((void**)&qkvbuf, g_qkv);
    cudaGetSymbolAddress((void**)&attbuf, g_att);

    // GroupNorm
    gn_partial_kernel<<<dim3(GN_SPLIT, 32), 256>>>(x);
    gn_finalize_kernel<<<32, 32>>>();
    gn_apply_kernel<<<(BATCH * CH * NPOS) / (256 * 4), 256>>>(x, norm_w, norm_b);

    // QKV projection: [768,256] x [256,4096] per batch
    sgemm_kernel<false><<<dim3(NPOS / 64, 768 / 64, BATCH), 256>>>(
        qkv_w, hbuf, qkv_b, nullptr, qkvbuf, 3 * CH, CH);

    // Attention
    cudaFuncSetAttribute(attn_kernel, cudaFuncAttributeMaxDynamicSharedMemorySize, ATTN_SMEM);
    attn_kernel<<<dim3(NPOS / 64, BATCH * NHEADS), 256, ATTN_SMEM>>>(qkvbuf, attbuf);

    // Output projection + bias + residual
    sgemm_kernel<true><<<dim3(NPOS / 64, CH / 64, BATCH), 256>>>(
        proj_w, attbuf, proj_b, x, out, CH, CH);
}